// round 17
// baseline (speedup 1.0000x reference)
#include <cuda_runtime.h>
#include <cuda_bf16.h>
#include <math.h>
#include <stdint.h>

#define NN 50000
#define EE 400000
#define FF 128
#define TF 384
typedef unsigned long long ull;
typedef __nv_bfloat16 bf16;

// chunk: Ah@0(3072) Al@3072 Wh@6144(6144) Wl@12288 -> 18432B; 3-stage ring
#define SM_CHUNK 18432
#define SM_TOTAL (3 * SM_CHUNK)

__device__ __forceinline__ uint32_t smem_u32(const void* p) {
    uint32_t a;
    asm("{ .reg .u64 t; cvta.to.shared.u64 t, %1; cvt.u32.u64 %0, t; }" : "=r"(a) : "l"(p));
    return a;
}
__device__ __forceinline__ void cpa16(uint32_t dst, const void* src) {
    asm volatile("cp.async.ca.shared.global [%0], [%1], 16;" :: "r"(dst), "l"(src));
}

// ---------------- device scratch ----------------
__device__ float g_phi[NN * TF];
__device__ float g_h[NN * 256];
__device__ float g_v[NN * TF];
__device__ float g_U[NN * TF];
__device__ float g_V[NN * TF];
__device__ float g_a[NN * TF];
__device__ float g_erbf[EE * 24];
__device__ float g_WwT[20 * TF];
__device__ int   g_cnt[NN];
__device__ int   g_off[NN + 1];
__device__ int   g_cur[NN];
__device__ int   g_eid[EE];
__device__ bf16  g_Wh[180224], g_Wl[180224];   // Wp1@0 Wp2@16384 Wu@65536 Wv@81920 Wu1@98304 Wu2@131072
__device__ bf16  g_embh[NN * 128], g_embl[NN * 128];
__device__ bf16  g_hidh[NN * 128], g_hidl[NN * 128];
__device__ bf16  g_hh[NN * 256], g_hl[NN * 256];
__device__ bf16  g_vh[NN * TF], g_vl[NN * TF];

// ---------------- CSR build ----------------
__global__ void k_zero_cnt() {
    int i = blockIdx.x * 256 + threadIdx.x;
    if (i < NN) g_cnt[i] = 0;
}
__global__ void k_count(const int* __restrict__ dst) {
    int e = blockIdx.x * 256 + threadIdx.x;
    if (e < EE) atomicAdd(&g_cnt[dst[e]], 1);
}
__global__ __launch_bounds__(1024) void k_scan() {
    __shared__ int ws[32];
    int tid = threadIdx.x, lane = tid & 31, wid = tid >> 5;
    const int C = 49;
    int b0 = tid * C, b1 = b0 + C; if (b1 > NN) b1 = NN;
    int sum = 0;
    for (int i = b0; i < b1; i++) sum += g_cnt[i];
    int v = sum;
    #pragma unroll
    for (int d = 1; d < 32; d <<= 1) {
        int y = __shfl_up_sync(0xffffffffu, v, d);
        if (lane >= d) v += y;
    }
    if (lane == 31) ws[wid] = v;
    __syncthreads();
    if (wid == 0) {
        int s = ws[lane];
        #pragma unroll
        for (int d = 1; d < 32; d <<= 1) {
            int y = __shfl_up_sync(0xffffffffu, s, d);
            if (lane >= d) s += y;
        }
        ws[lane] = s;
    }
    __syncthreads();
    int run = v - sum + (wid ? ws[wid - 1] : 0);
    for (int i = b0; i < b1; i++) {
        g_off[i] = run; g_cur[i] = run;
        run += g_cnt[i];
    }
    if (tid == 0) g_off[NN] = EE;
}
__global__ void k_scatter(const int* __restrict__ dst) {
    int e = blockIdx.x * 256 + threadIdx.x;
    if (e < EE) {
        int p = atomicAdd(&g_cur[dst[e]], 1);
        g_eid[p] = e;
    }
}
__global__ void k_wwt(const float* __restrict__ Ww) {
    int i = blockIdx.x * 256 + threadIdx.x;
    if (i < TF * 20) {
        int j = i / 20, k = i % 20;
        g_WwT[k * TF + j] = Ww[i];
    }
}

// ---------------- split kernels ----------------
__device__ __forceinline__ void split1(float x, bf16& h, bf16& l) {
    h = __float2bfloat16(x);
    l = __float2bfloat16(x - __bfloat162float(h));
}
__global__ void k_embsplit(const float* __restrict__ emb, const int* __restrict__ z) {
    int i = blockIdx.x * 256 + threadIdx.x;
    int n = i >> 7, f = i & 127;
    float x = emb[(size_t)z[n] * 128 + f];
    split1(x, g_embh[i], g_embl[i]);
}
__global__ void k_wsplit(const float* __restrict__ Wp1, const float* __restrict__ Wp2,
                         const float* __restrict__ Wu, const float* __restrict__ Wv,
                         const float* __restrict__ Wu1, const float* __restrict__ Wu2) {
    int i = blockIdx.x * 256 + threadIdx.x;
    if (i >= 180224) return;
    float x;
    if (i < 16384) x = Wp1[i];
    else if (i < 65536) x = Wp2[i - 16384];
    else if (i < 81920) x = Wu[i - 65536];
    else if (i < 98304) x = Wv[i - 81920];
    else if (i < 131072) x = Wu1[i - 98304];
    else x = Wu2[i - 131072];
    split1(x, g_Wh[i], g_Wl[i]);
}

// ---------------- per-edge dir + rbf ----------------
__global__ void k_edge(const float* __restrict__ pos, const int* __restrict__ src,
                       const int* __restrict__ dst) {
    int e = blockIdx.x * 256 + threadIdx.x;
    if (e >= EE) return;
    int s = src[e], d = dst[e];
    float rx = pos[d * 3 + 0] - pos[s * 3 + 0];
    float ry = pos[d * 3 + 1] - pos[s * 3 + 1];
    float rz = pos[d * 3 + 2] - pos[s * 3 + 2];
    float dist = sqrtf(rx * rx + ry * ry + rz * rz);
    dist = fmaxf(dist, 1e-9f);
    float inv = 1.0f / dist;
    float buf[24];
    buf[0] = rx * inv; buf[1] = ry * inv; buf[2] = rz * inv;
    float c = 3.14159265358979f * dist * 0.2f;
    float sc, cc; sincosf(c, &sc, &cc);
    float sn = sc, cn = cc;
    buf[3] = sn * inv;
    #pragma unroll
    for (int k = 1; k < 20; k++) {
        float sn2 = fmaf(sn, cc, cn * sc);
        float cn2 = fmaf(cn, cc, -sn * sc);
        sn = sn2; cn = cn2;
        buf[3 + k] = sn * inv;
    }
    buf[23] = 0.0f;
    float4* o = (float4*)(g_erbf + (size_t)e * 24);
    #pragma unroll
    for (int q = 0; q < 6; q++) o[q] = ((float4*)buf)[q];
}

// ---------------- gather accumulation ----------------
__global__ void __launch_bounds__(128) k_gather(const int* __restrict__ src,
                                                const float* __restrict__ bw,
                                                const float* __restrict__ emb,
                                                const int* __restrict__ z) {
    int t = threadIdx.x;
    float w0[20], w2[20];
    #pragma unroll
    for (int k = 0; k < 20; k++) {
        w0[k] = g_WwT[k * TF + t];
        w2[k] = g_WwT[k * TF + 256 + t];
    }
    float b0 = bw[t], b2 = bw[256 + t];
    int nbase = blockIdx.x * 32;
    for (int ii = 0; ii < 32; ii++) {
        int n = nbase + ii;
        if (n >= NN) break;
        int e0 = g_off[n], e1 = g_off[n + 1];
        float accs = 0.f, av0 = 0.f, av1 = 0.f, av2 = 0.f;
        int eC = 0, sC = 0;
        if (e0 < e1) { eC = g_eid[e0]; sC = __ldg(&src[eC]); }
        for (int idx = e0; idx < e1; idx++) {
            const float4* eb = (const float4*)(g_erbf + (size_t)eC * 24);
            float4 q0 = eb[0], q1 = eb[1], q2 = eb[2], q3 = eb[3], q4 = eb[4], q5 = eb[5];
            float p0 = g_phi[(size_t)sC * TF + t];
            float p2 = g_phi[(size_t)sC * TF + 256 + t];
            if (idx + 1 < e1) { eC = g_eid[idx + 1]; sC = __ldg(&src[eC]); }
            float r[20];
            r[0] = q0.w;
            r[1] = q1.x; r[2] = q1.y; r[3] = q1.z; r[4] = q1.w;
            r[5] = q2.x; r[6] = q2.y; r[7] = q2.z; r[8] = q2.w;
            r[9] = q3.x; r[10] = q3.y; r[11] = q3.z; r[12] = q3.w;
            r[13] = q4.x; r[14] = q4.y; r[15] = q4.z; r[16] = q4.w;
            r[17] = q5.x; r[18] = q5.y; r[19] = q5.z;
            float wf0 = b0, wf2 = b2;
            #pragma unroll
            for (int k = 0; k < 20; k++) {
                wf0 = fmaf(r[k], w0[k], wf0);
                wf2 = fmaf(r[k], w2[k], wf2);
            }
            float m2 = p2 * wf2;
            accs = fmaf(p0, wf0, accs);
            av0 = fmaf(m2, q0.x, av0);
            av1 = fmaf(m2, q0.y, av1);
            av2 = fmaf(m2, q0.z, av2);
        }
        int zn = z[n];
        float s = emb[(size_t)zn * 128 + t] + accs;
        g_h[n * 256 + t] = s;
        split1(s, g_hh[n * 256 + t], g_hl[n * 256 + t]);
        int i0 = (n * 3 + 0) * FF + t, i1 = (n * 3 + 1) * FF + t, i2 = (n * 3 + 2) * FF + t;
        g_v[i0] = av0; g_v[i1] = av1; g_v[i2] = av2;
        split1(av0, g_vh[i0], g_vl[i0]);
        split1(av1, g_vh[i1], g_vl[i1]);
        split1(av2, g_vh[i2], g_vl[i2]);
    }
}

// ---------------- tensor-core GEMM: 64x128 tile, warp tile 32x32 (no spills) ----------------
template <int KIN, int SILU, int OUTHL, int UVMODE>
__global__ void __launch_bounds__(256) tgemm(const bf16* __restrict__ Ah,
                                             const bf16* __restrict__ Al,
                                             const bf16* __restrict__ Wh,
                                             const bf16* __restrict__ Wl,
                                             const float* __restrict__ bias,
                                             const float* __restrict__ bias2,
                                             float* __restrict__ out,
                                             float* __restrict__ out2,
                                             bf16* __restrict__ oh, bf16* __restrict__ ol,
                                             int M, int ldo) {
    extern __shared__ __align__(16) char sm[];
    int tid = threadIdx.x, lane = tid & 31, wid = tid >> 5;
    int rowbase = blockIdx.x * 64;
    int nb = blockIdx.y;
    Wh += (size_t)nb * 128 * KIN;
    Wl += (size_t)nb * 128 * KIN;
    int colbase;
    if (UVMODE) {
        if (nb) { bias = bias2; out = out2; }
        colbase = 0;
    } else {
        bias += nb * 128;
        colbase = nb * 128;
    }

    uint32_t sb = smem_u32(sm);
    // staging: A seg (1 per thread): half=tid>>7, row=(tid&127)>>1, seg=tid&1
    int a_half = tid >> 7, a_row = (tid & 127) >> 1, a_seg = tid & 1;
    int arow_i = rowbase + a_row;
    const bf16* asrc = (a_half ? Al : Ah) + (size_t)(arow_i < M ? arow_i : 0) * KIN + a_seg * 8;
    uint32_t adst = sb + (a_half ? 3072u : 0u) + (uint32_t)a_row * 48 + a_seg * 16;
    // W segs (2 per thread): widx = tid, tid+256: half=widx>>8, row=(widx&255)>>1, seg=widx&1
    int w0_half = 0, w0_row = tid >> 1, w0_seg = tid & 1;
    const bf16* wsrc0 = Wh + (size_t)w0_row * KIN + w0_seg * 8;
    uint32_t wdst0 = sb + 6144u + (uint32_t)w0_row * 48 + w0_seg * 16;
    int w1_row = tid >> 1, w1_seg = tid & 1;
    const bf16* wsrc1 = Wl + (size_t)w1_row * KIN + w1_seg * 8;
    uint32_t wdst1 = sb + 12288u + (uint32_t)w1_row * 48 + w1_seg * 16;

    int warp_m = wid & 1, warp_n = wid >> 1;
    uint32_t a_ad = sb + (uint32_t)(warp_m * 32 + ((lane >> 3) & 1) * 8 + (lane & 7)) * 48
                  + ((lane >> 4) ? 16u : 0u);
    int l4 = lane & 15;
    uint32_t b_ad = sb + 6144u + (uint32_t)(warp_n * 32 + (l4 & 7)) * 48
                  + ((l4 >> 3) ? 16u : 0u);

    float acc[2][4][4];
    #pragma unroll
    for (int mf = 0; mf < 2; mf++)
        #pragma unroll
        for (int nf = 0; nf < 4; nf++)
            #pragma unroll
            for (int q = 0; q < 4; q++) acc[mf][nf][q] = 0.f;

    const int NCH = KIN / 16;
    #pragma unroll
    for (int c = 0; c < 2; c++) {
        uint32_t bo = c * SM_CHUNK;
        int ko = c * 16;
        cpa16(adst + bo, asrc + ko);
        cpa16(wdst0 + bo, wsrc0 + ko);
        cpa16(wdst1 + bo, wsrc1 + ko);
        asm volatile("cp.async.commit_group;");
    }
    for (int c = 0; c < NCH; c++) {
        if (c + 1 < NCH) asm volatile("cp.async.wait_group 1;");
        else             asm volatile("cp.async.wait_group 0;");
        __syncthreads();
        if (c + 2 < NCH) {
            uint32_t bo = ((c + 2) % 3) * SM_CHUNK;
            int ko = (c + 2) * 16;
            cpa16(adst + bo, asrc + ko);
            cpa16(wdst0 + bo, wsrc0 + ko);
            cpa16(wdst1 + bo, wsrc1 + ko);
            asm volatile("cp.async.commit_group;");
        }
        uint32_t bufo = (uint32_t)(c % 3) * SM_CHUNK;
        #pragma unroll
        for (int pass = 0; pass < 3; pass++) {
            uint32_t asel = bufo + ((pass == 2) ? 3072u : 0u);
            uint32_t wsel = bufo + ((pass == 1) ? 6144u : 0u);
            uint32_t bfr[4][2];
            #pragma unroll
            for (int nf = 0; nf < 4; nf++) {
                asm volatile("ldmatrix.sync.aligned.m8n8.x2.shared.b16 {%0,%1}, [%2];"
                             : "=r"(bfr[nf][0]), "=r"(bfr[nf][1])
                             : "r"(b_ad + wsel + nf * 384));
            }
            #pragma unroll
            for (int mf = 0; mf < 2; mf++) {
                uint32_t a0, a1, a2, a3;
                asm volatile("ldmatrix.sync.aligned.m8n8.x4.shared.b16 {%0,%1,%2,%3}, [%4];"
                             : "=r"(a0), "=r"(a1), "=r"(a2), "=r"(a3)
                             : "r"(a_ad + asel + mf * 768));
                #pragma unroll
                for (int nf = 0; nf < 4; nf++) {
                    asm volatile(
                        "mma.sync.aligned.m16n8k16.row.col.f32.bf16.bf16.f32 "
                        "{%0,%1,%2,%3},{%4,%5,%6,%7},{%8,%9},{%0,%1,%2,%3};"
                        : "+f"(acc[mf][nf][0]), "+f"(acc[mf][nf][1]),
                          "+f"(acc[mf][nf][2]), "+f"(acc[mf][nf][3])
                        : "r"(a0), "r"(a1), "r"(a2), "r"(a3),
                          "r"(bfr[nf][0]), "r"(bfr[nf][1]));
                }
            }
        }
    }

    // epilogue
    int g = lane >> 2, tg = lane & 3;
    #pragma unroll
    for (int nf = 0; nf < 4; nf++) {
        int col = warp_n * 32 + nf * 8 + tg * 2;
        float b0 = __ldg(&bias[col]), b1 = __ldg(&bias[col + 1]);
        #pragma unroll
        for (int mf = 0; mf < 2; mf++) {
            int r0 = rowbase + warp_m * 32 + mf * 16 + g;
            float x00 = acc[mf][nf][0] + b0, x01 = acc[mf][nf][1] + b1;
            float x10 = acc[mf][nf][2] + b0, x11 = acc[mf][nf][3] + b1;
            if (SILU) {
                x00 = x00 / (1.f + expf(-x00)); x01 = x01 / (1.f + expf(-x01));
                x10 = x10 / (1.f + expf(-x10)); x11 = x11 / (1.f + expf(-x11));
            }
            if (OUTHL) {
                if (r0 < M) {
                    bf16 h0, l0, h1, l1;
                    split1(x00, h0, l0); split1(x01, h1, l1);
                    size_t p = (size_t)r0 * 128 + colbase + col;
                    *(uint32_t*)&oh[p] = (uint32_t)__bfloat16_as_ushort(h0) | ((uint32_t)__bfloat16_as_ushort(h1) << 16);
                    *(uint32_t*)&ol[p] = (uint32_t)__bfloat16_as_ushort(l0) | ((uint32_t)__bfloat16_as_ushort(l1) << 16);
                }
                if (r0 + 8 < M) {
                    bf16 h0, l0, h1, l1;
                    split1(x10, h0, l0); split1(x11, h1, l1);
                    size_t p = (size_t)(r0 + 8) * 128 + colbase + col;
                    *(uint32_t*)&oh[p] = (uint32_t)__bfloat16_as_ushort(h0) | ((uint32_t)__bfloat16_as_ushort(h1) << 16);
                    *(uint32_t*)&ol[p] = (uint32_t)__bfloat16_as_ushort(l0) | ((uint32_t)__bfloat16_as_ushort(l1) << 16);
                }
            } else {
                if (r0 < M)
                    *(float2*)&out[(size_t)r0 * ldo + colbase + col] = make_float2(x00, x01);
                if (r0 + 8 < M)
                    *(float2*)&out[(size_t)(r0 + 8) * ldo + colbase + col] = make_float2(x10, x11);
            }
        }
    }
}

__global__ void k_vn() {
    int i = blockIdx.x * 256 + threadIdx.x;
    int n = i >> 7, f = i & 127;
    float x = g_V[(n * 3 + 0) * FF + f];
    float y = g_V[(n * 3 + 1) * FF + f];
    float z = g_V[(n * 3 + 2) * FF + f];
    float vn = sqrtf(x * x + y * y + z * z);
    split1(vn, g_hh[n * 256 + 128 + f], g_hl[n * 256 + 128 + f]);
}

__global__ void k_final(float* __restrict__ out) {
    int i = blockIdx.x * 256 + threadIdx.x;
    int n = i >> 7, f = i & 127;
    const float* ga = g_a + (size_t)n * TF;
    float a1 = ga[f], a2 = ga[128 + f], a3 = ga[256 + f];
    float dot = 0.f;
    float vo[3];
    #pragma unroll
    for (int c = 0; c < 3; c++) {
        int idx = (n * 3 + c) * FF + f;
        float Uc = g_U[idx], Vc = g_V[idx];
        dot = fmaf(Uc, Vc, dot);
        vo[c] = g_v[idx] + Uc * a1;
    }
    out[i] = g_h[n * 256 + f] + a2 + dot * a3;
    float* vp = out + (size_t)NN * FF + (size_t)i * 3;
    vp[0] = vo[0]; vp[1] = vo[1]; vp[2] = vo[2];
}

// ---------------- launch ----------------
extern "C" void kernel_launch(void* const* d_in, const int* in_sizes, int n_in,
                              void* d_out, int out_size) {
    const float* pos = (const float*)d_in[0];
    const float* emb = (const float*)d_in[1];
    const float* Wp1 = (const float*)d_in[2];
    const float* bp1 = (const float*)d_in[3];
    const float* Wp2 = (const float*)d_in[4];
    const float* bp2 = (const float*)d_in[5];
    const float* Ww  = (const float*)d_in[6];
    const float* bw  = (const float*)d_in[7];
    const float* Wu  = (const float*)d_in[8];
    const float* bu  = (const float*)d_in[9];
    const float* Wv  = (const float*)d_in[10];
    const float* bv  = (const float*)d_in[11];
    const float* Wu1 = (const float*)d_in[12];
    const float* bu1 = (const float*)d_in[13];
    const float* Wu2 = (const float*)d_in[14];
    const float* bu2 = (const float*)d_in[15];
    const int* z   = (const int*)d_in[16];
    const int* src = (const int*)d_in[17];
    const int* dst = (const int*)d_in[18];
    float* out = (float*)d_out;

    float *p_phi, *p_a, *p_U, *p_V;
    cudaGetSymbolAddress((void**)&p_phi, g_phi);
    cudaGetSymbolAddress((void**)&p_a, g_a);
    cudaGetSymbolAddress((void**)&p_U, g_U);
    cudaGetSymbolAddress((void**)&p_V, g_V);
    bf16 *p_Wh, *p_Wl, *p_embh, *p_embl, *p_hidh, *p_hidl, *p_hh, *p_hl, *p_vh, *p_vl;
    cudaGetSymbolAddress((void**)&p_Wh, g_Wh);
    cudaGetSymbolAddress((void**)&p_Wl, g_Wl);
    cudaGetSymbolAddress((void**)&p_embh, g_embh);
    cudaGetSymbolAddress((void**)&p_embl, g_embl);
    cudaGetSymbolAddress((void**)&p_hidh, g_hidh);
    cudaGetSymbolAddress((void**)&p_hidl, g_hidl);
    cudaGetSymbolAddress((void**)&p_hh, g_hh);
    cudaGetSymbolAddress((void**)&p_hl, g_hl);
    cudaGetSymbolAddress((void**)&p_vh, g_vh);
    cudaGetSymbolAddress((void**)&p_vl, g_vl);

    cudaFuncSetAttribute(tgemm<128, 1, 1, 0>, cudaFuncAttributeMaxDynamicSharedMemorySize, SM_TOTAL);
    cudaFuncSetAttribute(tgemm<128, 0, 0, 0>, cudaFuncAttributeMaxDynamicSharedMemorySize, SM_TOTAL);
    cudaFuncSetAttribute(tgemm<128, 0, 0, 1>, cudaFuncAttributeMaxDynamicSharedMemorySize, SM_TOTAL);
    cudaFuncSetAttribute(tgemm<256, 1, 1, 0>, cudaFuncAttributeMaxDynamicSharedMemorySize, SM_TOTAL);

    const int gridNF = (NN * FF) / 256;
    const int gridE  = (EE + 255) / 256;
    const int gridN  = (NN + 255) / 256;
    const int gridR  = (NN + 63) / 64;            // 782
    const int gridM3 = (NN * 3 + 63) / 64;        // 2344
    const int gridGather = (NN + 31) / 32;

    // 4th launch = phi L1 tgemm (profiled by ncu)
    k_embsplit<<<gridNF, 256>>>(emb, z);
    k_wsplit<<<(180224 + 255) / 256, 256>>>(Wp1, Wp2, Wu, Wv, Wu1, Wu2);
    k_zero_cnt<<<gridN, 256>>>();
    tgemm<128, 1, 1, 0><<<dim3(gridR, 1), 256, SM_TOTAL>>>(p_embh, p_embl, p_Wh, p_Wl, bp1, nullptr,
                                                           nullptr, nullptr, p_hidh, p_hidl, NN, 128);
    k_count<<<gridE, 256>>>(dst);
    k_scan<<<1, 1024>>>();
    k_scatter<<<gridE, 256>>>(dst);
    k_edge<<<gridE, 256>>>(pos, src, dst);
    k_wwt<<<(TF * 20 + 255) / 256, 256>>>(Ww);
    tgemm<128, 0, 0, 0><<<dim3(gridR, 3), 256, SM_TOTAL>>>(p_hidh, p_hidl, p_Wh + 16384, p_Wl + 16384,
                                                           bp2, nullptr, p_phi, nullptr, nullptr, nullptr, NN, 384);

    k_gather<<<gridGather, 128>>>(src, bw, emb, z);

    tgemm<128, 0, 0, 1><<<dim3(gridM3, 2), 256, SM_TOTAL>>>(p_vh, p_vl, p_Wh + 65536, p_Wl + 65536,
                                                            bu, bv, p_U, p_V, nullptr, nullptr, NN * 3, 128);
    k_vn<<<gridNF, 256>>>();
    tgemm<256, 1, 1, 0><<<dim3(gridR, 1), 256, SM_TOTAL>>>(p_hh, p_hl, p_Wh + 98304, p_Wl + 98304,
                                                           bu1, nullptr, nullptr, nullptr, p_hidh, p_hidl, NN, 128);
    tgemm<128, 0, 0, 0><<<dim3(gridR, 3), 256, SM_TOTAL>>>(p_hidh, p_hidl, p_Wh + 131072, p_Wl + 131072,
                                                           bu2, nullptr, p_a, nullptr, nullptr, nullptr, NN, 384);
    k_final<<<gridNF, 256>>>(out);
}